// round 1
// baseline (speedup 1.0000x reference)
#include <cuda_runtime.h>
#include <math.h>

#define Bc 8
#define Nc 1024
#define Mc 1024
#define Dc 1024
#define Hc 128
#define MBITS 32
#define NEG_INF __int_as_float(0xff800000)

static constexpr float kScale = 0.17677669529663687f; // 1/sqrt(32)

// ---------------- scratch (no allocations allowed) ----------------
__device__ float    g_qt[Bc * Nc * MBITS];   // tropical Q codes
__device__ float    g_qr[Bc * Nc * MBITS];   // real Q codes
__device__ unsigned g_qb[Bc * Nc];           // boolean Q bits
__device__ float    g_kt[Bc * Mc * MBITS];
__device__ float    g_kr[Bc * Mc * MBITS];
__device__ unsigned g_kb[Bc * Mc];
__device__ float    g_vp[Bc * Mc * Hc];      // V @ Wv

// ================================================================
// Kernel 1: fused Q (or K) projection: X[8192,1024] x {Wb,Wt,Wr}[1024,32]
// -> trop codes, real codes, packed boolean bits.
// Tile: 64 rows x 96 cols, BK=32, 256 threads, 4x6 microtile.
// ================================================================
__global__ __launch_bounds__(256) void proj_qk_kernel(
    const float* __restrict__ X,
    const float* __restrict__ Wb, const float* __restrict__ Wt,
    const float* __restrict__ Wr,
    float* __restrict__ oT, float* __restrict__ oR, unsigned* __restrict__ oB)
{
    __shared__ float As[64][33];
    __shared__ float Bs[32][96];
    __shared__ float sbool[64][33];

    const int tid = threadIdx.x;
    const int ty = tid >> 4;        // 0..15 -> 4 rows each
    const int tx = tid & 15;        // 0..15 -> 6 cols each
    const int row0 = blockIdx.x * 64;

    float acc[4][6];
#pragma unroll
    for (int i = 0; i < 4; i++)
#pragma unroll
        for (int j = 0; j < 6; j++) acc[i][j] = 0.f;

    for (int k0 = 0; k0 < Dc; k0 += 32) {
        // A tile: 64x32 floats, float4 loads
#pragma unroll
        for (int l = 0; l < 2; l++) {
            int idx = tid + l * 256;
            int r = idx >> 3, c = (idx & 7) * 4;
            float4 v = *(const float4*)(X + (size_t)(row0 + r) * Dc + k0 + c);
            As[r][c] = v.x; As[r][c + 1] = v.y; As[r][c + 2] = v.z; As[r][c + 3] = v.w;
        }
        // B tile: 32 k x 96 cols (cols 0-31 bool, 32-63 trop, 64-95 real)
#pragma unroll
        for (int l = 0; l < 12; l++) {
            int idx = tid + l * 256;
            int kk = idx / 96, j = idx % 96;
            const float* W = (j < 32) ? Wb : ((j < 64) ? Wt : Wr);
            Bs[kk][j] = W[(size_t)(k0 + kk) * 32 + (j & 31)];
        }
        __syncthreads();
#pragma unroll
        for (int kk = 0; kk < 32; kk++) {
            float a[4], bv[6];
#pragma unroll
            for (int i = 0; i < 4; i++) a[i] = As[ty * 4 + i][kk];
#pragma unroll
            for (int j = 0; j < 6; j++) bv[j] = Bs[kk][tx * 6 + j];
#pragma unroll
            for (int i = 0; i < 4; i++)
#pragma unroll
                for (int j = 0; j < 6; j++) acc[i][j] = fmaf(a[i], bv[j], acc[i][j]);
        }
        __syncthreads();
    }

    // scatter: trop/real to global, bool to smem for bit packing
#pragma unroll
    for (int i = 0; i < 4; i++) {
        int r = ty * 4 + i;
        int row = row0 + r;
#pragma unroll
        for (int j = 0; j < 6; j++) {
            int col = tx * 6 + j;
            float v = acc[i][j];
            if (col < 32)      sbool[r][col] = v;
            else if (col < 64) oT[(size_t)row * MBITS + (col - 32)] = v;
            else               oR[(size_t)row * MBITS + (col - 64)] = v;
        }
    }
    __syncthreads();
    if (tid < 64) {
        unsigned bits = 0;
#pragma unroll
        for (int j = 0; j < 32; j++)
            bits |= (sbool[tid][j] > 0.f ? 1u : 0u) << j;
        oB[row0 + tid] = bits;
    }
}

// ================================================================
// Kernel 2 (shared): C[rows,128] = A[rows,1024] x B[1024,128]
// Used for V@Wv (grid (128,1), bStride=0) and attn@VP (grid (16,8)).
// ================================================================
__global__ __launch_bounds__(256) void gemm128_kernel(
    const float* __restrict__ A, const float* __restrict__ B0,
    float* __restrict__ C, size_t bStride)
{
    __shared__ float As[64][33];
    __shared__ float Bs[32][128];

    const int tid = threadIdx.x;
    const int ty = tid >> 4;
    const int tx = tid & 15;
    const float* Bm = B0 + (size_t)blockIdx.y * bStride;
    const size_t row0 = ((size_t)blockIdx.y * gridDim.x + blockIdx.x) * 64;

    float acc[4][8];
#pragma unroll
    for (int i = 0; i < 4; i++)
#pragma unroll
        for (int j = 0; j < 8; j++) acc[i][j] = 0.f;

    for (int k0 = 0; k0 < 1024; k0 += 32) {
#pragma unroll
        for (int l = 0; l < 2; l++) {
            int idx = tid + l * 256;
            int r = idx >> 3, c = (idx & 7) * 4;
            float4 v = *(const float4*)(A + (row0 + r) * 1024 + k0 + c);
            As[r][c] = v.x; As[r][c + 1] = v.y; As[r][c + 2] = v.z; As[r][c + 3] = v.w;
        }
#pragma unroll
        for (int l = 0; l < 4; l++) {
            int idx = tid + l * 256;
            int kk = idx >> 5, c = (idx & 31) * 4;
            *(float4*)&Bs[kk][c] = *(const float4*)(Bm + (size_t)(k0 + kk) * 128 + c);
        }
        __syncthreads();
#pragma unroll
        for (int kk = 0; kk < 32; kk++) {
            float a[4];
#pragma unroll
            for (int i = 0; i < 4; i++) a[i] = As[ty * 4 + i][kk];
            float4 b0 = *(float4*)&Bs[kk][tx * 8];
            float4 b1 = *(float4*)&Bs[kk][tx * 8 + 4];
            float bb[8] = {b0.x, b0.y, b0.z, b0.w, b1.x, b1.y, b1.z, b1.w};
#pragma unroll
            for (int i = 0; i < 4; i++)
#pragma unroll
                for (int j = 0; j < 8; j++) acc[i][j] = fmaf(a[i], bb[j], acc[i][j]);
        }
        __syncthreads();
    }
#pragma unroll
    for (int i = 0; i < 4; i++) {
        float4 o0 = make_float4(acc[i][0], acc[i][1], acc[i][2], acc[i][3]);
        float4 o1 = make_float4(acc[i][4], acc[i][5], acc[i][6], acc[i][7]);
        float* cp = C + (row0 + ty * 4 + i) * 128 + tx * 8;
        *(float4*)cp = o0;
        *(float4*)(cp + 4) = o1;
    }
}

// ================================================================
// Kernel 3: fused monoid scores -> raw masked scaled scores.
// 64x64 tile per block, 256 threads, 4x4 pairs/thread.
// ================================================================
__global__ __launch_bounds__(256) void scores_kernel(
    const float* __restrict__ fw, const int* __restrict__ mask,
    float* __restrict__ attn)
{
    __shared__ float qt[64][32];
    __shared__ float qr[64][32];
    __shared__ float kts[32][68];   // transposed, padded
    __shared__ float krs[32][68];
    __shared__ unsigned qb_s[64];
    __shared__ unsigned kb_s[64];

    const int tid = threadIdx.x;
    const int b  = blockIdx.z;
    const int n0 = blockIdx.y * 64;
    const int m0 = blockIdx.x * 64;
    const int qbase = b * Nc + n0;
    const int kbase = b * Mc + m0;

    // load Q codes (row-major, float4)
#pragma unroll
    for (int l = 0; l < 2; l++) {
        int idx = tid + l * 256;
        int r = idx >> 3, c = (idx & 7) * 4;
        *(float4*)&qt[r][c] = *(const float4*)(g_qt + (size_t)(qbase + r) * MBITS + c);
        *(float4*)&qr[r][c] = *(const float4*)(g_qr + (size_t)(qbase + r) * MBITS + c);
    }
    // load K codes transposed
#pragma unroll
    for (int l = 0; l < 8; l++) {
        int idx = tid + l * 256;
        int r = idx >> 5, d = idx & 31;
        kts[d][r] = g_kt[(size_t)(kbase + r) * MBITS + d];
        krs[d][r] = g_kr[(size_t)(kbase + r) * MBITS + d];
    }
    if (tid < 64)            qb_s[tid]       = g_qb[qbase + tid];
    else if (tid < 128)      kb_s[tid - 64]  = g_kb[kbase + tid - 64];
    __syncthreads();

    const int tn0 = (tid >> 4) * 4;
    const int tm0 = (tid & 15) * 4;

    float tAcc[4][4], rAcc[4][4];
#pragma unroll
    for (int i = 0; i < 4; i++)
#pragma unroll
        for (int j = 0; j < 4; j++) { tAcc[i][j] = NEG_INF; rAcc[i][j] = 0.f; }

#pragma unroll
    for (int d0 = 0; d0 < 32; d0 += 4) {
        float qtl[4][4], qrl[4][4];
#pragma unroll
        for (int i = 0; i < 4; i++) {
            float4 t = *(float4*)&qt[tn0 + i][d0];
            float4 r = *(float4*)&qr[tn0 + i][d0];
            qtl[i][0] = t.x; qtl[i][1] = t.y; qtl[i][2] = t.z; qtl[i][3] = t.w;
            qrl[i][0] = r.x; qrl[i][1] = r.y; qrl[i][2] = r.z; qrl[i][3] = r.w;
        }
#pragma unroll
        for (int dd = 0; dd < 4; dd++) {
            float4 ktv = *(float4*)&kts[d0 + dd][tm0];
            float4 krv = *(float4*)&krs[d0 + dd][tm0];
            float ktl[4] = {ktv.x, ktv.y, ktv.z, ktv.w};
            float krl[4] = {krv.x, krv.y, krv.z, krv.w};
#pragma unroll
            for (int i = 0; i < 4; i++) {
                float qtd = qtl[i][dd];
                float qrd = qrl[i][dd];
#pragma unroll
                for (int j = 0; j < 4; j++) {
                    tAcc[i][j] = fmaxf(tAcc[i][j], qtd + ktl[j]);
                    rAcc[i][j] = fmaf(qrd, krl[j], rAcc[i][j]);
                }
            }
        }
    }

    // fusion weights softmax (3 elements)
    float f0 = fw[0], f1 = fw[1], f2 = fw[2];
    float fm = fmaxf(f0, fmaxf(f1, f2));
    float e0 = __expf(f0 - fm), e1 = __expf(f1 - fm), e2 = __expf(f2 - fm);
    float inv = 1.f / (e0 + e1 + e2);
    float w0 = e0 * inv, w1 = e1 * inv, w2 = e2 * inv;

    unsigned qbv[4], kbv[4];
#pragma unroll
    for (int i = 0; i < 4; i++) qbv[i] = qb_s[tn0 + i];
#pragma unroll
    for (int j = 0; j < 4; j++) kbv[j] = kb_s[tm0 + j];

#pragma unroll
    for (int i = 0; i < 4; i++) {
        size_t off = ((size_t)b * Nc + n0 + tn0 + i) * Mc + m0 + tm0;
        int4 mk = *(const int4*)(mask + off);
        float s0 = (w0 * (float)(32 - __popc(qbv[i] ^ kbv[0])) + w1 * tAcc[i][0] + w2 * rAcc[i][0]) * kScale;
        float s1 = (w0 * (float)(32 - __popc(qbv[i] ^ kbv[1])) + w1 * tAcc[i][1] + w2 * rAcc[i][1]) * kScale;
        float s2 = (w0 * (float)(32 - __popc(qbv[i] ^ kbv[2])) + w1 * tAcc[i][2] + w2 * rAcc[i][2]) * kScale;
        float s3 = (w0 * (float)(32 - __popc(qbv[i] ^ kbv[3])) + w1 * tAcc[i][3] + w2 * rAcc[i][3]) * kScale;
        float4 o;
        o.x = (mk.x == 0) ? NEG_INF : s0;
        o.y = (mk.y == 0) ? NEG_INF : s1;
        o.z = (mk.z == 0) ? NEG_INF : s2;
        o.w = (mk.w == 0) ? NEG_INF : s3;
        *(float4*)(attn + off) = o;
    }
}

// ================================================================
// Kernel 4: row softmax over M=1024, in place. One block per row.
// ================================================================
__global__ __launch_bounds__(256) void softmax_kernel(float* __restrict__ attn)
{
    __shared__ float red[8];
    const size_t row = blockIdx.x;
    float* p = attn + row * (size_t)Mc;
    const int tid = threadIdx.x;
    const int lane = tid & 31, wid = tid >> 5;

    float4 v = *(float4*)(p + tid * 4);
    float m = fmaxf(fmaxf(v.x, v.y), fmaxf(v.z, v.w));
#pragma unroll
    for (int o = 16; o > 0; o >>= 1) m = fmaxf(m, __shfl_xor_sync(0xffffffffu, m, o));
    if (lane == 0) red[wid] = m;
    __syncthreads();
    float bm = fmaxf(fmaxf(fmaxf(red[0], red[1]), fmaxf(red[2], red[3])),
                     fmaxf(fmaxf(red[4], red[5]), fmaxf(red[6], red[7])));
    __syncthreads();

    float4 e;
    e.x = __expf(v.x - bm); e.y = __expf(v.y - bm);
    e.z = __expf(v.z - bm); e.w = __expf(v.w - bm);
    float s = e.x + e.y + e.z + e.w;
#pragma unroll
    for (int o = 16; o > 0; o >>= 1) s += __shfl_xor_sync(0xffffffffu, s, o);
    if (lane == 0) red[wid] = s;
    __syncthreads();
    float ts = red[0] + red[1] + red[2] + red[3] + red[4] + red[5] + red[6] + red[7];
    float invs = 1.f / ts;
    e.x *= invs; e.y *= invs; e.z *= invs; e.w *= invs;
    *(float4*)(p + tid * 4) = e;
}

// ================================================================
extern "C" void kernel_launch(void* const* d_in, const int* in_sizes, int n_in,
                              void* d_out, int out_size)
{
    const float* Q   = (const float*)d_in[0];
    const float* K   = (const float*)d_in[1];
    const float* V   = (const float*)d_in[2];
    const float* Wqb = (const float*)d_in[3];
    const float* Wkb = (const float*)d_in[4];
    const float* Wqt = (const float*)d_in[5];
    const float* Wkt = (const float*)d_in[6];
    const float* Wqr = (const float*)d_in[7];
    const float* Wkr = (const float*)d_in[8];
    const float* Wv  = (const float*)d_in[9];
    const float* fw  = (const float*)d_in[10];
    const int*   mask = (const int*)d_in[11];

    float* out  = (float*)d_out;                             // [B,N,128]
    float* attn = (float*)d_out + (size_t)Bc * Nc * Hc;      // [B,N,M]

    float *qt, *qr, *kt, *kr, *vp;
    unsigned *qb, *kb;
    cudaGetSymbolAddress((void**)&qt, g_qt);
    cudaGetSymbolAddress((void**)&qr, g_qr);
    cudaGetSymbolAddress((void**)&qb, g_qb);
    cudaGetSymbolAddress((void**)&kt, g_kt);
    cudaGetSymbolAddress((void**)&kr, g_kr);
    cudaGetSymbolAddress((void**)&kb, g_kb);
    cudaGetSymbolAddress((void**)&vp, g_vp);

    // projections
    proj_qk_kernel<<<128, 256>>>(Q, Wqb, Wqt, Wqr, qt, qr, qb);
    proj_qk_kernel<<<128, 256>>>(K, Wkb, Wkt, Wkr, kt, kr, kb);
    gemm128_kernel<<<dim3(128, 1), 256>>>(V, Wv, vp, (size_t)0);

    // fused monoid scores (masked, scaled)
    scores_kernel<<<dim3(16, 16, 8), 256>>>(fw, mask, attn);

    // softmax over M
    softmax_kernel<<<Bc * Nc, 256>>>(attn);

    // out = attn @ VP  (per batch)
    gemm128_kernel<<<dim3(16, 8), 256>>>(attn, vp, out, (size_t)Mc * Hc);
}